// round 5
// baseline (speedup 1.0000x reference)
#include <cuda_runtime.h>
#include <cuda_bf16.h>
#include <cstdint>

// CrossAttentionModel_20684562497797
//
// Reference math collapses: softmax over a size-1 axis == 1.0 exactly for any
// finite input (inputs are finite Gaussians, weights finite -> scores finite,
// no NaN/Inf path). mean over heads of ones == 1.0. Output is ones((2048,2048))
// independent of all inputs. The only mandatory work is writing 16 MiB of 1.0f.
//
// Store-bandwidth-bound fill: STG.128 (float4), grid-stride, unroll 4 for MLP.

__global__ __launch_bounds__(256, 8)
void fill_ones_kernel(float4* __restrict__ out4, int n4,
                      float* __restrict__ out_tail, int n_total) {
    const float4 one4 = make_float4(1.0f, 1.0f, 1.0f, 1.0f);
    int idx = blockIdx.x * blockDim.x + threadIdx.x;
    int stride = gridDim.x * blockDim.x;

    // Main vectorized body: 4 independent STG.128 in flight per thread per iter.
    #pragma unroll 4
    for (int i = idx; i < n4; i += stride) {
        out4[i] = one4;
    }

    // Scalar tail (out_size = 4M is divisible by 4; this is a robustness guard).
    int tail_start = n4 * 4;
    for (int i = tail_start + idx; i < n_total; i += stride) {
        out_tail[i] = 1.0f;
    }
}

extern "C" void kernel_launch(void* const* d_in, const int* in_sizes, int n_in,
                              void* d_out, int out_size) {
    (void)d_in; (void)in_sizes; (void)n_in;

    float* out = (float*)d_out;
    int n4 = out_size / 4;

    // 148 SMs x 4 CTAs, 256 threads: enough in-flight 128B stores to hit the
    // LTS/DRAM store ceiling; grid-stride keeps it exact for any out_size.
    const int threads = 256;
    const int blocks = 148 * 4;

    fill_ones_kernel<<<blocks, threads>>>((float4*)out, n4, out, out_size);
}